// round 2
// baseline (speedup 1.0000x reference)
#include <cuda_runtime.h>
#include <math.h>

#define BATCH 4
#define SEQ   4096
#define DIM   256
#define TOPK  32
#define ROWS  (BATCH*SEQ)

#define TQ   128     // queries per CTA in attn kernel
#define TK   128     // keys per tile
#define BK   8       // k-depth per smem stage
#define SSTR 132     // score smem row stride (floats), 4t+j mod 32 -> low conflict, float4-aligned

// Scratch for q, k, v projections (allocation-free contract: __device__ globals)
__device__ float g_q[ROWS*DIM];
__device__ float g_k[ROWS*DIM];
__device__ float g_v[ROWS*DIM];

// ---------------------------------------------------------------------------
// Kernel 1: fused QKV projection.  out = x @ W + b  for each of q,k,v.
// Tile: 128x128x(BK=8), 256 threads, 8x8 microtile per thread.
// grid = (ROWS/128, DIM/128, 3)
// ---------------------------------------------------------------------------
__global__ __launch_bounds__(256)
void qkv_kernel(const float* __restrict__ x,
                const float* __restrict__ Wq, const float* __restrict__ bq,
                const float* __restrict__ Wk, const float* __restrict__ bk,
                const float* __restrict__ Wv, const float* __restrict__ bv)
{
    __shared__ float As[BK*128];   // As[kk][mm]
    __shared__ float Bs[BK*128];   // Bs[kk][nn]

    const int which = blockIdx.z;
    const float* W    = (which==0) ? Wq : (which==1) ? Wk : Wv;
    const float* bias = (which==0) ? bq : (which==1) ? bk : bv;
    float* outp       = (which==0) ? g_q : (which==1) ? g_k : g_v;

    const int tid = threadIdx.x;
    const int tx = tid & 15, ty = tid >> 4;
    const int row0 = blockIdx.x * 128;
    const int col0 = blockIdx.y * 128;

    float acc[8][8];
    #pragma unroll
    for (int i = 0; i < 8; i++)
        #pragma unroll
        for (int j = 0; j < 8; j++) acc[i][j] = 0.f;

    const int amm = tid >> 1;          // row within A tile
    const int akk = (tid & 1) * 4;     // k offset (float4)
    const int bkk = tid >> 5;          // k row of B tile
    const int bnn = (tid & 31) * 4;    // col offset (float4)

    for (int k0 = 0; k0 < DIM; k0 += BK) {
        // A: x[row0+mm, k0+kk] -> As[kk][mm]  (transposed store)
        float4 av = *(const float4*)&x[(row0 + amm)*DIM + k0 + akk];
        As[(akk+0)*128 + amm] = av.x;
        As[(akk+1)*128 + amm] = av.y;
        As[(akk+2)*128 + amm] = av.z;
        As[(akk+3)*128 + amm] = av.w;
        // B: W[k0+kk, col0+nn] -> Bs[kk][nn]  (direct, coalesced)
        *(float4*)&Bs[bkk*128 + bnn] = *(const float4*)&W[(k0 + bkk)*DIM + col0 + bnn];
        __syncthreads();
        #pragma unroll
        for (int kk = 0; kk < BK; kk++) {
            float a[8], b[8];
            *(float4*)&a[0] = *(const float4*)&As[kk*128 + ty*8];
            *(float4*)&a[4] = *(const float4*)&As[kk*128 + ty*8 + 4];
            *(float4*)&b[0] = *(const float4*)&Bs[kk*128 + tx*8];
            *(float4*)&b[4] = *(const float4*)&Bs[kk*128 + tx*8 + 4];
            #pragma unroll
            for (int i = 0; i < 8; i++)
                #pragma unroll
                for (int j = 0; j < 8; j++)
                    acc[i][j] = fmaf(a[i], b[j], acc[i][j]);
        }
        __syncthreads();
    }

    #pragma unroll
    for (int i = 0; i < 8; i++) {
        const int r = row0 + ty*8 + i;
        #pragma unroll
        for (int j = 0; j < 8; j += 4) {
            const int c = col0 + tx*8 + j;
            float4 o;
            o.x = acc[i][j+0] + bias[c+0];
            o.y = acc[i][j+1] + bias[c+1];
            o.z = acc[i][j+2] + bias[c+2];
            o.w = acc[i][j+3] + bias[c+3];
            *(float4*)&outp[r*DIM + c] = o;
        }
    }
}

// ---------------------------------------------------------------------------
// Kernel 2: fused scores + running top-32 + softmax + AV gather.
// One CTA per (batch, 128-query tile): grid = BATCH * (SEQ/TQ) = 128 CTAs.
// ---------------------------------------------------------------------------
__global__ __launch_bounds__(256)
void attn_kernel(float* __restrict__ out)
{
    extern __shared__ float sm[];
    float* As   = sm;                    // [BK][128]  q chunk (transposed)
    float* Bs   = As  + BK*128;          // [BK][128]  k chunk (transposed)
    float* Ssc  = Bs  + BK*128;          // [128][SSTR] staged scores
    float* topV = Ssc + 128*SSTR;        // [128][TOPK] sorted desc values
    int*   topI = (int*)(topV + 128*TOPK); // [128][TOPK]

    const int tid = threadIdx.x;
    const int tx = tid & 15, ty = tid >> 4;
    const int b  = blockIdx.x >> 5;       // SEQ/TQ = 32 q-tiles per batch
    const int qt = blockIdx.x & 31;
    const int q0 = qt * TQ;               // query offset within batch
    const float* qb = g_q + b*SEQ*DIM;
    const float* kb = g_k + b*SEQ*DIM;
    const float* vb = g_v + b*SEQ*DIM;

    for (int i = tid; i < 128*TOPK; i += 256) topV[i] = -INFINITY;
    __syncthreads();

    float thr = -INFINITY;                // per-owned-query running 32nd value

    const int amm = tid >> 1;
    const int akk = (tid & 1) * 4;

    for (int kt = 0; kt < SEQ/TK; kt++) {
        const int kbase = kt * TK;

        float acc[8][8];
        #pragma unroll
        for (int i = 0; i < 8; i++)
            #pragma unroll
            for (int j = 0; j < 8; j++) acc[i][j] = 0.f;

        for (int k0 = 0; k0 < DIM; k0 += BK) {
            float4 av = *(const float4*)&qb[(q0 + amm)*DIM + k0 + akk];
            As[(akk+0)*128 + amm] = av.x;
            As[(akk+1)*128 + amm] = av.y;
            As[(akk+2)*128 + amm] = av.z;
            As[(akk+3)*128 + amm] = av.w;
            float4 kv = *(const float4*)&kb[(kbase + amm)*DIM + k0 + akk];
            Bs[(akk+0)*128 + amm] = kv.x;
            Bs[(akk+1)*128 + amm] = kv.y;
            Bs[(akk+2)*128 + amm] = kv.z;
            Bs[(akk+3)*128 + amm] = kv.w;
            __syncthreads();
            #pragma unroll
            for (int kk = 0; kk < BK; kk++) {
                float a[8], bb[8];
                *(float4*)&a[0]  = *(const float4*)&As[kk*128 + ty*8];
                *(float4*)&a[4]  = *(const float4*)&As[kk*128 + ty*8 + 4];
                *(float4*)&bb[0] = *(const float4*)&Bs[kk*128 + tx*8];
                *(float4*)&bb[4] = *(const float4*)&Bs[kk*128 + tx*8 + 4];
                #pragma unroll
                for (int i = 0; i < 8; i++)
                    #pragma unroll
                    for (int j = 0; j < 8; j++)
                        acc[i][j] = fmaf(a[i], bb[j], acc[i][j]);
            }
            __syncthreads();
        }

        // stage scores: Ssc[query][key]
        #pragma unroll
        for (int i = 0; i < 8; i++)
            #pragma unroll
            for (int j = 0; j < 8; j += 4)
                *(float4*)&Ssc[(ty*8 + i)*SSTR + tx*8 + j] = *(float4*)&acc[i][j];
        __syncthreads();

        // running top-k update: thread qq owns query qq (threads 0..127)
        if (tid < TQ) {
            const int qq = tid;
            float* tv = topV + qq*TOPK;
            int*   ti = topI + qq*TOPK;
            #pragma unroll 4
            for (int j = 0; j < TK; j++) {
                float s = Ssc[qq*SSTR + j];
                if (s > thr) {
                    int p = TOPK - 1;
                    while (p > 0 && tv[p-1] < s) {
                        tv[p] = tv[p-1];
                        ti[p] = ti[p-1];
                        p--;
                    }
                    tv[p] = s;
                    ti[p] = kbase + j;
                    thr = tv[TOPK-1];
                }
            }
        }
        __syncthreads();
    }

    // softmax over the 32 kept values (sorted desc -> tv[0] is max)
    if (tid < TQ) {
        float* tv = topV + tid*TOPK;
        float m = tv[0];
        float ssum = 0.f;
        #pragma unroll
        for (int j = 0; j < TOPK; j++) {
            float e = expf(tv[j] - m);
            tv[j] = e;
            ssum += e;
        }
        float inv = 1.f / ssum;
        #pragma unroll
        for (int j = 0; j < TOPK; j++) tv[j] *= inv;
    }
    __syncthreads();

    // AV: out[q, d] = sum_j p_j * v[idx_j, d]; thread = one d column (256 = DIM)
    const int d = tid;
    float* orow0 = out + ((size_t)b*SEQ + q0)*DIM;
    for (int qq = 0; qq < TQ; qq++) {
        float accv = 0.f;
        #pragma unroll
        for (int j = 0; j < TOPK; j++) {
            float p  = topV[qq*TOPK + j];   // broadcast LDS
            int  idx = topI[qq*TOPK + j];   // broadcast LDS
            accv = fmaf(p, vb[idx*DIM + d], accv);  // coalesced, L2-resident
        }
        orow0[qq*DIM + d] = accv;
    }
}

static const int ATTN_SMEM_BYTES =
    (BK*128 + BK*128 + 128*SSTR + 128*TOPK) * (int)sizeof(float)
    + 128*TOPK * (int)sizeof(int);   // = 108,544 bytes

extern "C" void kernel_launch(void* const* d_in, const int* in_sizes, int n_in,
                              void* d_out, int out_size)
{
    const float* x  = (const float*)d_in[0];
    const float* Wq = (const float*)d_in[1];
    const float* bq = (const float*)d_in[2];
    const float* Wk = (const float*)d_in[3];
    const float* bk = (const float*)d_in[4];
    const float* Wv = (const float*)d_in[5];
    const float* bv = (const float*)d_in[6];
    float* out = (float*)d_out;

    // idempotent, host-side, not a stream op -> graph-capture safe
    cudaFuncSetAttribute(attn_kernel,
                         cudaFuncAttributeMaxDynamicSharedMemorySize,
                         ATTN_SMEM_BYTES);

    dim3 g1(ROWS/128, DIM/128, 3);
    qkv_kernel<<<g1, 256>>>(x, Wq, bq, Wk, bk, Wv, bv);

    attn_kernel<<<BATCH*(SEQ/TQ), 256, ATTN_SMEM_BYTES>>>(out);
}